// round 17
// baseline (speedup 1.0000x reference)
#include <cuda_runtime.h>
#include <cuda_fp16.h>

// out = segment_sum(source[src_idx], seg_ids); softmax over singleton axis==1,
// so all attention machinery is dead code.
//
// f32 gather is pinned at the L2/LTS bandwidth ceiling (410MB / ~34.5us ~=
// 11.9 TB/s). fp16 halves the L2 bytes (205MB -> 17us floor) but was
// issue-bound; this round cuts the issue stream: the uniform-oct fast path
// sums the 8 gathered half2 values with a 7-instruction HADD2 tree and does
// ONE half2->float2 convert + 2 FADD per oct (was 8 CVT + 14 FADD). Accuracy:
// 3 half roundings/oct ~ 2.5e-4 rel + 2.1e-4 storage << 1e-3 budget.
//
//  K1 prep: source f32 -> fp16 scratch (convert only).
//  K2 zero_boundary: zero exactly the rows that receive atomicAdd (each gather
//     warp's first and last segment under the closed-form partition).
//  K3 gather: lane = one half2 (2 cols); warp gather = 128B row = 1 L1
//     wavefront / 1 L2 line per edge. 8 independent gathers per oct, loads
//     batched at iteration top. Interior flush = STG, boundary = atomicAdd.
//
// Inputs: 0 source[N,64] f32, 2 src_idx[E] i32, 3 seg_ids[E] i32 (sorted).

#define N_NODES_MAX 100000
#define NBLOCKS 1184
#define NTHREADS 256
#define NWARPS (NBLOCKS * (NTHREADS / 32))

__device__ __half2 g_src_h2[N_NODES_MAX * 32];   // 12.8 MB fp16 source

__global__ void __launch_bounds__(NTHREADS)
prep_kernel(const float2* __restrict__ src2, int n_h2) {
    int i = blockIdx.x * blockDim.x + threadIdx.x;
    int stride = gridDim.x * blockDim.x;
    for (int j = i; j < n_h2; j += stride)
        g_src_h2[j] = __float22half2_rn(src2[j]);
}

// warp w's edge range [e0, e1) under the balanced oct partition
__device__ __forceinline__ void warp_range(int w, int E, int* pe0, int* pe1) {
    const int noct_total = (E + 7) >> 3;
    const int q = noct_total / NWARPS;
    const int r = noct_total - q * NWARPS;
    const int o0 = w * q + (w < r ? w : r);
    const int cnt = q + (w < r ? 1 : 0);
    int e0 = o0 << 3;
    int e1 = e0 + (cnt << 3);
    if (e1 > E) e1 = E;
    *pe0 = e0;
    *pe1 = (cnt == 0) ? e0 : e1;
}

// zero exactly the rows that will receive atomicAdd from the gather kernel
__global__ void __launch_bounds__(NTHREADS)
zero_boundary_kernel(const int* __restrict__ seg_ids,
                     float* __restrict__ out, int E) {
    const int t = blockIdx.x * (NTHREADS / 32) + (threadIdx.x >> 5);
    const int lane = threadIdx.x & 31;
    const int w = t >> 1;
    if (w >= NWARPS) return;
    int e0, e1;
    warp_range(w, E, &e0, &e1);
    if (e1 <= e0) return;
    int e = (t & 1) ? (e1 - 1) : e0;
    int row = __ldg(&seg_ids[e]);
    ((float2*)&out[(long long)row * 64])[lane] = make_float2(0.f, 0.f);
}

__global__ void __launch_bounds__(NTHREADS)
seg_gather_sum_kernel(const int4* __restrict__ src_idx4,
                      const int4* __restrict__ seg_ids4,
                      float* __restrict__ out,
                      int E) {
    const __half2* __restrict__ srcH = g_src_h2;
    const int* __restrict__ src_idx = (const int*)src_idx4;
    const int* __restrict__ seg_ids = (const int*)seg_ids4;

    const int lane = threadIdx.x & 31;
    const int warp = blockIdx.x * (NTHREADS / 32) + (threadIdx.x >> 5);

    int e, e1;
    warp_range(warp, E, &e, &e1);
    if (e1 <= e) return;

    const int first_seg = seg_ids[e];
    int cur = first_seg;
    float ax = 0.f, ay = 0.f;

#define FLUSH()                                                         \
    do {                                                                \
        float2* p = (float2*)&out[(long long)cur * 64 + 2 * lane];      \
        if (cur == first_seg) {                                         \
            atomicAdd(&((float*)p)[0], ax);                             \
            atomicAdd(&((float*)p)[1], ay);                             \
        } else {                                                        \
            *p = make_float2(ax, ay);                                   \
        }                                                               \
        ax = 0.f; ay = 0.f;                                             \
    } while (0)

#define ACC(S, H)                                                       \
    do {                                                                \
        if ((S) != cur) { FLUSH(); cur = (S); }                         \
        float2 _f = __half22float2(H);                                  \
        ax += _f.x; ay += _f.y;                                         \
    } while (0)

    int noct = (e1 - e) >> 3;
    for (int t = 0; t < noct; ++t, e += 8) {
        int4 sa = __ldg(&seg_ids4[(e >> 2) + 0]);
        int4 sb = __ldg(&seg_ids4[(e >> 2) + 1]);
        int4 ia = __ldg(&src_idx4[(e >> 2) + 0]);
        int4 ib = __ldg(&src_idx4[(e >> 2) + 1]);

        __half2 v0 = __ldg(&srcH[(long long)ia.x * 32 + lane]);
        __half2 v1 = __ldg(&srcH[(long long)ia.y * 32 + lane]);
        __half2 v2 = __ldg(&srcH[(long long)ia.z * 32 + lane]);
        __half2 v3 = __ldg(&srcH[(long long)ia.w * 32 + lane]);
        __half2 v4 = __ldg(&srcH[(long long)ib.x * 32 + lane]);
        __half2 v5 = __ldg(&srcH[(long long)ib.y * 32 + lane]);
        __half2 v6 = __ldg(&srcH[(long long)ib.z * 32 + lane]);
        __half2 v7 = __ldg(&srcH[(long long)ib.w * 32 + lane]);

        if (sa.x == sb.w) {
            // whole oct in one segment: 7 HADD2 + 1 CVT + 2 FADD
            if (sa.x != cur) { FLUSH(); cur = sa.x; }
            __half2 s01 = __hadd2(v0, v1);
            __half2 s23 = __hadd2(v2, v3);
            __half2 s45 = __hadd2(v4, v5);
            __half2 s67 = __hadd2(v6, v7);
            __half2 sA = __hadd2(s01, s23);
            __half2 sB = __hadd2(s45, s67);
            __half2 s  = __hadd2(sA, sB);
            float2 f = __half22float2(s);
            ax += f.x; ay += f.y;
        } else {
            ACC(sa.x, v0);
            ACC(sa.y, v1);
            ACC(sa.z, v2);
            ACC(sa.w, v3);
            ACC(sb.x, v4);
            ACC(sb.y, v5);
            ACC(sb.z, v6);
            ACC(sb.w, v7);
        }
    }

    // tail (E % 8 != 0 only in the last warp's range)
    for (; e < e1; ++e) {
        int s = __ldg(&seg_ids[e]);
        int idx = __ldg(&src_idx[e]);
        __half2 v = __ldg(&srcH[(long long)idx * 32 + lane]);
        ACC(s, v);
    }
#undef ACC
#undef FLUSH

    // running segment may continue into the next warp's range -> atomic
    atomicAdd(&out[(long long)cur * 64 + 2 * lane + 0], ax);
    atomicAdd(&out[(long long)cur * 64 + 2 * lane + 1], ay);
}

extern "C" void kernel_launch(void* const* d_in, const int* in_sizes, int n_in,
                              void* d_out, int out_size) {
    const float* source  = (const float*)d_in[0];
    const int*   src_idx = (const int*)d_in[2];
    const int*   seg_ids = (const int*)d_in[3];
    float* out = (float*)d_out;

    int E = in_sizes[2];
    int n_h2 = in_sizes[0] / 2;

    // K1: fp16 conversion of source
    prep_kernel<<<NBLOCKS, NTHREADS>>>((const float2*)source, n_h2);

    // K2: zero exactly the atomic-target rows (2 per gather warp)
    int nzwarps = NWARPS * 2;
    int nzblocks = (nzwarps + (NTHREADS / 32) - 1) / (NTHREADS / 32);
    zero_boundary_kernel<<<nzblocks, NTHREADS>>>(seg_ids, out, E);

    // K3: gather + segment-sum, single balanced wave
    seg_gather_sum_kernel<<<NBLOCKS, NTHREADS>>>(
        (const int4*)src_idx, (const int4*)seg_ids, out, E);
}